// round 5
// baseline (speedup 1.0000x reference)
#include <cuda_runtime.h>
#include <cstdint>

// Problem constants
#define H      2048
#define W      2048
#define FC_IN  1024
#define FC_OUT 10
#define NROWS  4096          // flat rows = H*W/FC_IN

// RNN pipeline config
#define NBLK   32            // pipeline stages (blocks), 64 rows each
#define CH     8             // columns per chunk
#define NCH    512           // chunks; NCH*CH = 4096 (cols 0..4094 used, 4095 pad)
#define NCSK   4096          // padded skewed width

// Static device scratch (no allocation allowed)
__device__ float g_inp[(size_t)NCSK * H];     // inp_cm[c][r]: scaled affine input, 32 MB
__device__ float g_acts[(size_t)NCSK * H];    // acts_cm[c][r]: h state per skewed col, 32 MB
__device__ float g_bnd[NBLK][NCSK + 64];      // boundary-row stream per block
__device__ int   g_flag[NBLK];                // chunk progress flags

// Acquire load for flag probes: formally pairs with the writer's st.release.gpu,
// so all subsequent (weak) data loads observe the published g_bnd values.
// R3's weak ld.cg probe raced: flag could land in its L2 slice before the data
// reached other slices. Acquire closes that window.
static __device__ __forceinline__ int ld_acq_i(const int* p) {
    int v; asm volatile("ld.acquire.gpu.global.s32 %0, [%1];" : "=r"(v) : "l"(p)); return v;
}
static __device__ __forceinline__ float ld_cg_f(const float* p) {
    float v; asm volatile("ld.global.cg.f32 %0, [%1];" : "=f"(v) : "l"(p)); return v;
}
static __device__ __forceinline__ void st_rel_i(int* p, int v) {
    asm volatile("st.release.gpu.global.s32 [%0], %1;" :: "l"(p), "r"(v) : "memory");
}

// tanh(y) with z = y * 2*log2(e): tanh(y) = 1 - 2/(1 + 2^z). ~1e-6 accurate.
__device__ __forceinline__ float tanh_core(float z) {
    float e; asm("ex2.approx.f32 %0, %1;" : "=f"(e) : "f"(z));
    float d = e + 1.0f;
    float r; asm("rcp.approx.f32 %0, %1;" : "=f"(r) : "f"(d));
    return fmaf(-2.0f, r, 1.0f);
}

// ---------------------------------------------------------------------------
// Kernel 1: skew + input affine, row-major x -> skewed-column-major g_inp.
// inp_cm[c][r] = wL * (0 <= c-r < W ? x[r][c-r] : 0) + cL.
// smem shear-transpose tile: coalesced x reads, coalesced g_inp writes.
// Also resets the pipeline flags (stream-ordered before rnn_kernel).
// ---------------------------------------------------------------------------
__global__ void __launch_bounds__(256) skew_kernel(
    const float* __restrict__ x,
    const float* __restrict__ w_in, const float* __restrict__ b_in,
    const float* __restrict__ b_state)
{
    __shared__ float xs[32][66];   // pitch 66 -> diagonal smem reads conflict-free

    if (blockIdx.x == 0 && blockIdx.y == 0) {
        int t = threadIdx.y * 32 + threadIdx.x;
        if (t < NBLK) g_flag[t] = 0;
    }

    const float L2E2 = 2.8853900817779268f;   // 2*log2(e)
    const float wL = w_in[0] * L2E2;
    const float cL = (b_state[0] + b_in[0]) * L2E2;

    const int c0 = blockIdx.x * 32;           // skewed-column tile base (0..4095)
    const int r0 = blockIdx.y * 32;           // row tile base
    const int xb = c0 - r0 - 31;              // x-column window base

    // Load x[r0+rr][xb .. xb+63] (row-major, coalesced), OOB -> 0
    for (int rr = threadIdx.y; rr < 32; rr += 8) {
        const float* xrow = x + (size_t)(r0 + rr) * W;
        #pragma unroll
        for (int tt = 0; tt < 2; tt++) {
            int t = threadIdx.x + tt * 32;
            int xc = xb + t;
            xs[rr][t] = ((unsigned)xc < W) ? xrow[xc] : 0.0f;
        }
    }
    __syncthreads();

    // Write inp_cm[c0+cc][r0+rr] (column-major, coalesced over rr = lane)
    for (int cc = threadIdx.y; cc < 32; cc += 8) {
        int rr = threadIdx.x;
        float v = xs[rr][cc - rr + 31];       // = x[r][(c0+cc)-(r0+rr)] or 0
        g_inp[(size_t)(c0 + cc) * H + (r0 + rr)] = fmaf(wL, v, cL);
    }
}

// ---------------------------------------------------------------------------
// Kernel 2: diagonal-wavefront RNN. 32 blocks x 1 warp; block b owns rows
// [64b, 64b+64), lane owns rows r0 = 64b+2*lane and r0+1 (interleaved).
// h_new[r] = tanh(k0*h_old[r-1] + k1*h_old[r] + inp_cm[c][r])   (pre-scaled)
// Inter-block boundary handoff: chunked flags, writer release-stores, reader
// ACQUIRE-loads every probe (one chunk early so the L2 round trip and the
// acquire's ordering stall on later loads are hidden under the j-loop chain).
// ---------------------------------------------------------------------------
__global__ void __launch_bounds__(32, 1) rnn_kernel(const float* __restrict__ w_state)
{
    const int blk  = blockIdx.x;
    const int lane = threadIdx.x;

    const float L2E2 = 2.8853900817779268f;
    const float k0L = w_state[0] * L2E2;
    const float k1L = w_state[1] * L2E2;

    const int r0 = blk * 64 + lane * 2;
    const int HP = H / 2;                               // float2 per column
    const float2* __restrict__ inp2  = ((const float2*)g_inp)  + (r0 >> 1);
    float2*       __restrict__ acts2 = ((float2*)g_acts)       + (r0 >> 1);

    const int*   fptr = (blk > 0) ? &g_flag[blk - 1] : &g_flag[0];
    const float* bptr = (blk > 0) ? g_bnd[blk - 1]   : g_bnd[0];

    float h0 = 0.0f, h1 = 0.0f;
    float2 pin[CH], pinn[CH];

    // Prologue: inputs for chunk 0; boundary for chunk 0 (cols -1..CH-2)
    #pragma unroll
    for (int j = 0; j < CH; j++) pin[j] = inp2[(size_t)j * HP];

    float bval = 0.0f;
    int fprobe = 0;
    if (blk > 0) {
        do { fprobe = ld_acq_i(fptr); } while (fprobe < 1);
        if (lane > 0) bval = ld_cg_f(bptr + (lane - 1));
        // lane 0 at chunk 0 needs h[-1] = 0 (initial state)
    }

    const bool wlast  = (lane == 31);
    const bool haspub = (blk < NBLK - 1);

    for (int k = 0; k < NCH; k++) {
        const int  c0       = k * CH;
        const bool havenext = (k + 1 < NCH);

        // Prefetch NEXT chunk's boundary (lane j -> col (k+1)*CH - 1 + j).
        // fprobe is an acquire result from one chunk ago -> usually already
        // >= tgt: no reload, and sync is already established by that acquire.
        float bvaln = 0.0f;
        if (blk > 0 && havenext) {
            const int tgt = k + 2;
            while (fprobe < tgt) fprobe = ld_acq_i(fptr);
            bvaln  = ld_cg_f(bptr + (c0 + CH - 1 + lane));   // in flight over j-loop
            fprobe = ld_acq_i(fptr);                          // probe for chunk k+1's check
        }
        // Prefetch NEXT chunk's inputs (coalesced LDG.64, in flight over j-loop)
        if (havenext) {
            #pragma unroll
            for (int j = 0; j < CH; j++)
                pinn[j] = inp2[(size_t)(c0 + CH + j) * HP];
        }

        float2* ao = acts2 + (size_t)c0 * HP;
        #pragma unroll
        for (int j = 0; j < CH; j++) {
            float xn = __shfl_up_sync(0xffffffffu, h1, 1);   // old h[r0-1] (lanes>0)
            float bb = __shfl_sync(0xffffffffu, bval, j);    // boundary for lane 0
            if (lane == 0) xn = bb;
            float z0 = fmaf(k0L, xn, fmaf(k1L, h0, pin[j].x));
            float z1 = fmaf(k0L, h0, fmaf(k1L, h1, pin[j].y)); // uses OLD h0
            h0 = tanh_core(z0);
            h1 = tanh_core(z1);
            ao[(size_t)j * HP] = make_float2(h0, h1);        // coalesced STG.64
            if (wlast && haspub) g_bnd[blk][c0 + j] = h1;    // stream bottom row
        }

        // Publish chunk k complete: release store orders the g_bnd data first
        if (haspub && wlast) st_rel_i(&g_flag[blk], k + 1);

        // Rotate double buffers (loads completed during j-loop)
        bval = bvaln;
        if (havenext) {
            #pragma unroll
            for (int j = 0; j < CH; j++) pin[j] = pinn[j];
        }
    }
}

// ---------------------------------------------------------------------------
// Kernel 3: FC. flat[i][k] = unskewed[r][c] = acts_cm[r + c][r],
// with r = i>>1, c = (i&1)*1024 + k. Warp per output row, weights in smem.
// Diagonal gather is uncoalesced but spread over 512 blocks -> ~15us.
// ---------------------------------------------------------------------------
__global__ void __launch_bounds__(256) fc_kernel(
    const float* __restrict__ fcw, const float* __restrict__ fcb,
    float* __restrict__ out)
{
    __shared__ float ws[FC_OUT * FC_IN];   // 40 KB
    int tid = threadIdx.x;
    for (int i = tid; i < FC_OUT * FC_IN; i += 256) ws[i] = fcw[i];
    __syncthreads();

    int warp = tid >> 5, lane = tid & 31;
    int i = blockIdx.x * 8 + warp;         // flat row 0..4095
    int r = i >> 1, half = i & 1;
    const float* base = g_acts + (size_t)(r + half * FC_IN) * H + r;

    float xv[32];
    #pragma unroll
    for (int m = 0; m < 32; m++) xv[m] = base[(size_t)(lane + 32 * m) * H];

    #pragma unroll
    for (int j = 0; j < FC_OUT; j++) {
        float s = 0.0f;
        #pragma unroll
        for (int m = 0; m < 32; m++)
            s = fmaf(xv[m], ws[j * FC_IN + lane + 32 * m], s);
        #pragma unroll
        for (int o = 16; o > 0; o >>= 1)
            s += __shfl_xor_sync(0xffffffffu, s, o);
        if (lane == 0) out[i * FC_OUT + j] = s + fcb[j];
    }
}

extern "C" void kernel_launch(void* const* d_in, const int* in_sizes, int n_in,
                              void* d_out, int out_size)
{
    const float* x       = (const float*)d_in[0];  // [1, 2048, 2048]
    const float* w_in    = (const float*)d_in[1];  // [1,1,1,1]
    const float* b_in    = (const float*)d_in[2];  // [1]
    const float* w_state = (const float*)d_in[3];  // [1,1,2]
    const float* b_state = (const float*)d_in[4];  // [1]
    const float* fc_w    = (const float*)d_in[5];  // [10, 1024]
    const float* fc_b    = (const float*)d_in[6];  // [10]
    float* out = (float*)d_out;                    // [4096, 10]

    // Stream-ordered: skew (also resets flags) -> rnn -> fc. Graph-capturable.
    skew_kernel<<<dim3(NCSK / 32, H / 32), dim3(32, 8)>>>(x, w_in, b_in, b_state);
    // 32 blocks <= 148 SMs: whole pipeline co-resident in wave 1, spins safe.
    rnn_kernel<<<NBLK, 32>>>(w_state);
    fc_kernel<<<NROWS / 8, 256>>>(fc_w, fc_b, out);
}

// round 8
// speedup vs baseline: 1.4811x; 1.4811x over previous
#include <cuda_runtime.h>
#include <cstdint>

// Problem constants
#define H      2048
#define W      2048
#define FC_IN  1024
#define FC_OUT 10
#define NROWS  4096          // flat rows = H*W/FC_IN

// RNN pipeline config
#define NBLK   32            // pipeline stages (blocks), 64 rows each
#define CH     16            // columns per chunk
#define NCH    256           // chunks; NCH*CH = 4096 (cols 0..4094 used, 4095 pad)
#define NCSK   4096          // padded skewed width

// Static device scratch (no allocation allowed)
__device__ float g_inp[(size_t)NCSK * H];     // inp_cm[c][r]: scaled affine input, 32 MB
__device__ float g_acts[(size_t)NCSK * H];    // acts_cm[c][r]: h state per skewed col, 32 MB
__device__ float g_bnd[NBLK][NCSK + 64];      // boundary-row stream per block
__device__ int   g_flag[NBLK];                // chunk progress flags

// Acquire probe pairs with writer's st.release.gpu (proven in R4).
static __device__ __forceinline__ int ld_acq_i(const int* p) {
    int v; asm volatile("ld.acquire.gpu.global.s32 %0, [%1];" : "=r"(v) : "l"(p)); return v;
}
static __device__ __forceinline__ float ld_cg_f(const float* p) {
    float v; asm volatile("ld.global.cg.f32 %0, [%1];" : "=f"(v) : "l"(p)); return v;
}
static __device__ __forceinline__ void st_rel_i(int* p, int v) {
    asm volatile("st.release.gpu.global.s32 [%0], %1;" :: "l"(p), "r"(v) : "memory");
}

// tanh(y) with z = y * 2*log2(e): tanh(y) = 1 - 2/(1 + 2^z). ~1e-6 accurate.
__device__ __forceinline__ float tanh_core(float z) {
    float e; asm("ex2.approx.f32 %0, %1;" : "=f"(e) : "f"(z));
    float d = e + 1.0f;
    float r; asm("rcp.approx.f32 %0, %1;" : "=f"(r) : "f"(d));
    return fmaf(-2.0f, r, 1.0f);
}

// ---------------------------------------------------------------------------
// Kernel 1: skew + input affine, row-major x -> skewed-column-major g_inp.
// inp_cm[c][r] = wL * (0 <= c-r < W ? x[r][c-r] : 0) + cL.
// Also resets pipeline flags (stream-ordered before rnn_kernel each replay).
// ---------------------------------------------------------------------------
__global__ void __launch_bounds__(256) skew_kernel(
    const float* __restrict__ x,
    const float* __restrict__ w_in, const float* __restrict__ b_in,
    const float* __restrict__ b_state)
{
    __shared__ float xs[32][66];   // pitch 66 -> diagonal smem reads conflict-free

    if (blockIdx.x == 0 && blockIdx.y == 0) {
        int t = threadIdx.y * 32 + threadIdx.x;
        if (t < NBLK) g_flag[t] = 0;
    }

    const float L2E2 = 2.8853900817779268f;   // 2*log2(e)
    const float wL = w_in[0] * L2E2;
    const float cL = (b_state[0] + b_in[0]) * L2E2;

    const int c0 = blockIdx.x * 32;           // skewed-column tile base
    const int r0 = blockIdx.y * 32;           // row tile base
    const int xb = c0 - r0 - 31;              // x-column window base

    for (int rr = threadIdx.y; rr < 32; rr += 8) {
        const float* xrow = x + (size_t)(r0 + rr) * W;
        #pragma unroll
        for (int tt = 0; tt < 2; tt++) {
            int t = threadIdx.x + tt * 32;
            int xc = xb + t;
            xs[rr][t] = ((unsigned)xc < W) ? xrow[xc] : 0.0f;
        }
    }
    __syncthreads();

    for (int cc = threadIdx.y; cc < 32; cc += 8) {
        int rr = threadIdx.x;
        float v = xs[rr][cc - rr + 31];       // = x[r][(c0+cc)-(r0+rr)] or 0
        g_inp[(size_t)(c0 + cc) * H + (r0 + rr)] = fmaf(wL, v, cL);
    }
}

// ---------------------------------------------------------------------------
// Kernel 2: diagonal-wavefront RNN. 32 blocks x 1 warp; block b owns rows
// [64b, 64b+64), lane owns rows r0 = 64b+2*lane and r0+1.
// h_new[r] = tanh(k0*h_old[r-1] + k1*h_old[r] + inp_cm[c][r])   (pre-scaled)
//
// Boundary dataflow is the R2/R4-PROVEN scheme: all lanes preload bval
// (lane j holds the value for column c0+j), per-column warp broadcast,
// lane-0 override. Handshake: writer release-stores flag per chunk; reader
// acquire-polls one chunk early. Input prefetch is issued BEFORE the acquire
// (g_inp is constant during this kernel) so the spin never delays it.
// NO reader threadfence (R2's per-chunk L1 flush was the dominant cost).
// ---------------------------------------------------------------------------
__global__ void __launch_bounds__(32, 1) rnn_kernel(const float* __restrict__ w_state)
{
    const int blk  = blockIdx.x;
    const int lane = threadIdx.x;

    const float L2E2 = 2.8853900817779268f;
    const float k0L = w_state[0] * L2E2;
    const float k1L = w_state[1] * L2E2;

    const int r0 = blk * 64 + lane * 2;
    const int HP = H / 2;                               // float2 per column
    const float2* __restrict__ inp2  = ((const float2*)g_inp)  + (r0 >> 1);
    float2*       __restrict__ acts2 = ((float2*)g_acts)       + (r0 >> 1);

    const int*   fptr = (blk > 0) ? &g_flag[blk - 1] : &g_flag[0];
    const float* bptr = (blk > 0) ? g_bnd[blk - 1]   : g_bnd[0];

    const bool wlast  = (lane == 31);
    const bool haspub = (blk < NBLK - 1);

    float h0 = 0.0f, h1 = 0.0f;
    float2 pin[CH], pinn[CH];

    // Prologue: inputs + boundary for chunk 0 (cols -1..CH-2; col -1 -> h=0).
    // Lanes >= CH load unpublished slots but are never consumed (j < CH).
    #pragma unroll
    for (int j = 0; j < CH; j++) pin[j] = inp2[(size_t)j * HP];

    float bval = 0.0f;
    int fprobe = 0;
    if (blk > 0) {
        do { fprobe = ld_acq_i(fptr); } while (fprobe < 1);
        if (lane > 0) bval = ld_cg_f(bptr + (lane - 1));
    }

    for (int k = 0; k < NCH; k++) {
        const int  c0       = k * CH;
        const bool havenext = (k + 1 < NCH);

        // 1) Next-chunk INPUT prefetch first — flag-independent, in flight
        //    across the whole j-loop regardless of the acquire below.
        if (havenext) {
            #pragma unroll
            for (int j = 0; j < CH; j++)
                pinn[j] = inp2[(size_t)(c0 + CH + j) * HP];
        }

        // 2) Next-chunk BOUNDARY prefetch: lane j holds col c0+CH-1+j.
        //    fprobe is last chunk's acquire result -> usually >= tgt, no spin.
        float bvaln = 0.0f;
        if (blk > 0 && havenext) {
            const int tgt = k + 2;
            while (fprobe < tgt) fprobe = ld_acq_i(fptr);
            bvaln  = ld_cg_f(bptr + (c0 + CH - 1 + lane));   // in flight over j-loop
            fprobe = ld_acq_i(fptr);                          // head start, next check
        }

        float2* ao = acts2 + (size_t)c0 * HP;
        #pragma unroll
        for (int j = 0; j < CH; j++) {
            float xn = __shfl_up_sync(0xffffffffu, h1, 1);   // old h[r0-1], lanes>0
            float bb = __shfl_sync(0xffffffffu, bval, j);    // boundary for lane 0
            if (lane == 0) xn = bb;
            float z0 = fmaf(k0L, xn, fmaf(k1L, h0, pin[j].x));
            float z1 = fmaf(k0L, h0, fmaf(k1L, h1, pin[j].y)); // uses OLD h0
            h0 = tanh_core(z0);
            h1 = tanh_core(z1);
            ao[(size_t)j * HP] = make_float2(h0, h1);        // coalesced STG.64
            if (wlast && haspub) g_bnd[blk][c0 + j] = h1;    // bottom-row stream
        }

        // Publish chunk k: release orders the g_bnd data stores first.
        if (haspub && wlast) st_rel_i(&g_flag[blk], k + 1);

        // Rotate double buffers (loads completed during j-loop).
        bval = bvaln;
        if (havenext) {
            #pragma unroll
            for (int j = 0; j < CH; j++) pin[j] = pinn[j];
        }
    }
}

// ---------------------------------------------------------------------------
// Kernel 3: FC. flat[i][k] = unskewed[r][c] = acts_cm[r + c][r],
// with r = i>>1, c = (i&1)*1024 + k. Warp per output row, weights in smem.
// ---------------------------------------------------------------------------
__global__ void __launch_bounds__(256) fc_kernel(
    const float* __restrict__ fcw, const float* __restrict__ fcb,
    float* __restrict__ out)
{
    __shared__ float ws[FC_OUT * FC_IN];   // 40 KB
    int tid = threadIdx.x;
    for (int i = tid; i < FC_OUT * FC_IN; i += 256) ws[i] = fcw[i];
    __syncthreads();

    int warp = tid >> 5, lane = tid & 31;
    int i = blockIdx.x * 8 + warp;         // flat row 0..4095
    int r = i >> 1, half = i & 1;
    const float* base = g_acts + (size_t)(r + half * FC_IN) * H + r;

    float xv[32];
    #pragma unroll
    for (int m = 0; m < 32; m++) xv[m] = base[(size_t)(lane + 32 * m) * H];

    #pragma unroll
    for (int j = 0; j < FC_OUT; j++) {
        float s = 0.0f;
        #pragma unroll
        for (int m = 0; m < 32; m++)
            s = fmaf(xv[m], ws[j * FC_IN + lane + 32 * m], s);
        #pragma unroll
        for (int o = 16; o > 0; o >>= 1)
            s += __shfl_xor_sync(0xffffffffu, s, o);
        if (lane == 0) out[i * FC_OUT + j] = s + fcb[j];
    }
}

extern "C" void kernel_launch(void* const* d_in, const int* in_sizes, int n_in,
                              void* d_out, int out_size)
{
    const float* x       = (const float*)d_in[0];  // [1, 2048, 2048]
    const float* w_in    = (const float*)d_in[1];  // [1,1,1,1]
    const float* b_in    = (const float*)d_in[2];  // [1]
    const float* w_state = (const float*)d_in[3];  // [1,1,2]
    const float* b_state = (const float*)d_in[4];  // [1]
    const float* fc_w    = (const float*)d_in[5];  // [10, 1024]
    const float* fc_b    = (const float*)d_in[6];  // [10]
    float* out = (float*)d_out;                    // [4096, 10]

    // Stream-ordered: skew (also resets flags) -> rnn -> fc. Graph-capturable.
    skew_kernel<<<dim3(NCSK / 32, H / 32), dim3(32, 8)>>>(x, w_in, b_in, b_state);
    // 32 blocks <= 148 SMs: whole pipeline co-resident in wave 1, spins safe.
    rnn_kernel<<<NBLK, 32>>>(w_state);
    fc_kernel<<<NROWS / 8, 256>>>(fc_w, fc_b, out);
}

// round 9
// speedup vs baseline: 1.9923x; 1.3452x over previous
#include <cuda_runtime.h>
#include <cstdint>

// Problem constants
#define H      2048
#define W      2048
#define FC_IN  1024
#define FC_OUT 10
#define NROWS  4096          // flat rows = H*W/FC_IN

// RNN pipeline config
#define NBLK   32            // pipeline stages (blocks), 64 rows each
#define CH     16            // columns per chunk
#define NCH    256           // chunks; NCH*CH = 4096 (cols 0..4094 used, 4095 pad)
#define NCSK   4096          // padded skewed width

// Static device scratch (no allocation allowed)
__device__ float g_inp[(size_t)NCSK * H];     // inp_cm[c][r]: scaled affine input, 32 MB
__device__ float g_acts[(size_t)NCSK * H];    // acts_cm[c][r]: h state per skewed col, 32 MB
__device__ float g_bnd[NBLK][NCSK + 64];      // boundary-row stream per block
__device__ int   g_flag[NBLK];                // chunk progress flags

// Acquire probe pairs with writer's st.release.gpu (proven R4/R7).
static __device__ __forceinline__ int ld_acq_i(const int* p) {
    int v; asm volatile("ld.acquire.gpu.global.s32 %0, [%1];" : "=r"(v) : "l"(p)); return v;
}
static __device__ __forceinline__ float ld_cg_f(const float* p) {
    float v; asm volatile("ld.global.cg.f32 %0, [%1];" : "=f"(v) : "l"(p)); return v;
}
static __device__ __forceinline__ void st_rel_i(int* p, int v) {
    asm volatile("st.release.gpu.global.s32 [%0], %1;" :: "l"(p), "r"(v) : "memory");
}

// tanh(y) with z = y * 2*log2(e): tanh(y) = 1 - 2/(1 + 2^z). ~1e-6 accurate.
__device__ __forceinline__ float tanh_core(float z) {
    float e; asm("ex2.approx.f32 %0, %1;" : "=f"(e) : "f"(z));
    float d = e + 1.0f;
    float r; asm("rcp.approx.f32 %0, %1;" : "=f"(r) : "f"(d));
    return fmaf(-2.0f, r, 1.0f);
}

// ---------------------------------------------------------------------------
// Kernel 1: skew + input affine, row-major x -> skewed-column-major g_inp.
// inp_cm[c][r] = wL * (0 <= c-r < W ? x[r][c-r] : 0) + cL.
// Also resets pipeline flags (stream-ordered before rnn_kernel each replay).
// ---------------------------------------------------------------------------
__global__ void __launch_bounds__(256) skew_kernel(
    const float* __restrict__ x,
    const float* __restrict__ w_in, const float* __restrict__ b_in,
    const float* __restrict__ b_state)
{
    __shared__ float xs[32][66];   // pitch 66 -> diagonal smem reads conflict-free

    if (blockIdx.x == 0 && blockIdx.y == 0) {
        int t = threadIdx.y * 32 + threadIdx.x;
        if (t < NBLK) g_flag[t] = 0;
    }

    const float L2E2 = 2.8853900817779268f;   // 2*log2(e)
    const float wL = w_in[0] * L2E2;
    const float cL = (b_state[0] + b_in[0]) * L2E2;

    const int c0 = blockIdx.x * 32;           // skewed-column tile base
    const int r0 = blockIdx.y * 32;           // row tile base
    const int xb = c0 - r0 - 31;              // x-column window base

    for (int rr = threadIdx.y; rr < 32; rr += 8) {
        const float* xrow = x + (size_t)(r0 + rr) * W;
        #pragma unroll
        for (int tt = 0; tt < 2; tt++) {
            int t = threadIdx.x + tt * 32;
            int xc = xb + t;
            xs[rr][t] = ((unsigned)xc < W) ? xrow[xc] : 0.0f;
        }
    }
    __syncthreads();

    for (int cc = threadIdx.y; cc < 32; cc += 8) {
        int rr = threadIdx.x;
        float v = xs[rr][cc - rr + 31];       // = x[r][(c0+cc)-(r0+rr)] or 0
        g_inp[(size_t)(c0 + cc) * H + (r0 + rr)] = fmaf(wL, v, cL);
    }
}

// ---------------------------------------------------------------------------
// Kernel 2: diagonal-wavefront RNN, WARP-SPECIALIZED. 32 blocks x 2 warps.
// Block b owns rows [64b, 64b+64); compute lane owns rows 2l and 2l+1.
//
// Warp 1 (producer): per chunk, LDGs next chunk's inputs into smem, does the
// acquire-poll + boundary load into smem. All long-latency / ordered memory
// ops live here, OFF the recurrence warp.
// Warp 0 (compute): pure chain — LDS refill (off-chain), SHFL, FMA, MUFU,
// fire-and-forget STG of acts + boundary row, release-store of the flag.
// Handoff protocol, window math, and arithmetic are IDENTICAL to proven R7.
// One __syncthreads per chunk swaps the double buffers.
// ---------------------------------------------------------------------------
__global__ void __launch_bounds__(64, 1) rnn_kernel(const float* __restrict__ w_state)
{
    __shared__ float2 sin2[2][CH][32];   // staged inputs: [buf][col][lane], 8 KB
    __shared__ float  sbnd[2][32];       // staged boundary: [buf][lane]

    const int blk  = blockIdx.x;
    const int wid  = threadIdx.x >> 5;
    const int lane = threadIdx.x & 31;

    if (wid == 1) {
        // ================= PRODUCER WARP =================
        const float2* __restrict__ inp2 = ((const float2*)g_inp) + (blk * 32 + lane);
        const int*   fptr = (blk > 0) ? &g_flag[blk - 1] : &g_flag[0];
        const float* bptr = (blk > 0) ? g_bnd[blk - 1]   : g_bnd[0];
        const int HP = H / 2;

        // Prologue: fill buffer 0 (chunk 0)
        #pragma unroll
        for (int j = 0; j < CH; j++)
            sin2[0][j][lane] = inp2[(size_t)j * HP];
        float b0 = 0.0f;
        if (blk > 0) {
            int fp; do { fp = ld_acq_i(fptr); } while (fp < 1);
            if (lane > 0) b0 = ld_cg_f(bptr + (lane - 1));  // lane j -> col j-1
        }
        sbnd[0][lane] = b0;
        __syncthreads();

        for (int k = 0; k < NCH; k++) {
            if (k + 1 < NCH) {
                const int c0 = k * CH;
                const int nb = (k + 1) & 1;
                #pragma unroll
                for (int j = 0; j < CH; j++)
                    sin2[nb][j][lane] = inp2[(size_t)(c0 + CH + j) * HP];
                float bv = 0.0f;
                if (blk > 0) {
                    const int tgt = k + 2;
                    int fp; do { fp = ld_acq_i(fptr); } while (fp < tgt);
                    bv = ld_cg_f(bptr + (c0 + CH - 1 + lane));   // lane j -> col c0+CH-1+j
                }
                sbnd[nb][lane] = bv;
            }
            __syncthreads();
        }
    } else {
        // ================= COMPUTE WARP =================
        const float L2E2 = 2.8853900817779268f;
        const float k0L = w_state[0] * L2E2;
        const float k1L = w_state[1] * L2E2;

        const int HP = H / 2;
        float2* __restrict__ acts2 = ((float2*)g_acts) + (blk * 32 + lane);

        const bool wlast  = (lane == 31);
        const bool haspub = (blk < NBLK - 1);

        float h0 = 0.0f, h1 = 0.0f;

        __syncthreads();   // buffer 0 ready

        for (int k = 0; k < NCH; k++) {
            const int c0 = k * CH;
            const int cb = k & 1;

            // Refill registers from smem (LDS lat ~29, conflict-free, off-chain)
            float2 pin[CH];
            #pragma unroll
            for (int j = 0; j < CH; j++) pin[j] = sin2[cb][j][lane];
            float bval = sbnd[cb][lane];

            float2* ao = acts2 + (size_t)c0 * HP;
            #pragma unroll
            for (int j = 0; j < CH; j++) {
                float xn = __shfl_up_sync(0xffffffffu, h1, 1);   // old h[r-1], lanes>0
                float bb = __shfl_sync(0xffffffffu, bval, j);    // boundary for lane 0
                if (lane == 0) xn = bb;
                float z0 = fmaf(k0L, xn, fmaf(k1L, h0, pin[j].x));
                float z1 = fmaf(k0L, h0, fmaf(k1L, h1, pin[j].y)); // uses OLD h0
                h0 = tanh_core(z0);
                h1 = tanh_core(z1);
                ao[(size_t)j * HP] = make_float2(h0, h1);        // coalesced STG.64
                if (wlast && haspub) g_bnd[blk][c0 + j] = h1;    // bottom-row stream
            }

            // Publish chunk k: release orders this thread's g_bnd stores first.
            if (haspub && wlast) st_rel_i(&g_flag[blk], k + 1);

            __syncthreads();   // swap buffers (producer filled k+1)
        }
    }
}

// ---------------------------------------------------------------------------
// Kernel 3: FC. flat[i][k] = unskewed[r][c] = acts_cm[r + c][r],
// with r = i>>1, c = (i&1)*1024 + k. Warp per output row, weights in smem.
// ---------------------------------------------------------------------------
__global__ void __launch_bounds__(256) fc_kernel(
    const float* __restrict__ fcw, const float* __restrict__ fcb,
    float* __restrict__ out)
{
    __shared__ float ws[FC_OUT * FC_IN];   // 40 KB
    int tid = threadIdx.x;
    for (int i = tid; i < FC_OUT * FC_IN; i += 256) ws[i] = fcw[i];
    __syncthreads();

    int warp = tid >> 5, lane = tid & 31;
    int i = blockIdx.x * 8 + warp;         // flat row 0..4095
    int r = i >> 1, half = i & 1;
    const float* base = g_acts + (size_t)(r + half * FC_IN) * H + r;

    float xv[32];
    #pragma unroll
    for (int m = 0; m < 32; m++) xv[m] = base[(size_t)(lane + 32 * m) * H];

    #pragma unroll
    for (int j = 0; j < FC_OUT; j++) {
        float s = 0.0f;
        #pragma unroll
        for (int m = 0; m < 32; m++)
            s = fmaf(xv[m], ws[j * FC_IN + lane + 32 * m], s);
        #pragma unroll
        for (int o = 16; o > 0; o >>= 1)
            s += __shfl_xor_sync(0xffffffffu, s, o);
        if (lane == 0) out[i * FC_OUT + j] = s + fcb[j];
    }
}

extern "C" void kernel_launch(void* const* d_in, const int* in_sizes, int n_in,
                              void* d_out, int out_size)
{
    const float* x       = (const float*)d_in[0];  // [1, 2048, 2048]
    const float* w_in    = (const float*)d_in[1];  // [1,1,1,1]
    const float* b_in    = (const float*)d_in[2];  // [1]
    const float* w_state = (const float*)d_in[3];  // [1,1,2]
    const float* b_state = (const float*)d_in[4];  // [1]
    const float* fc_w    = (const float*)d_in[5];  // [10, 1024]
    const float* fc_b    = (const float*)d_in[6];  // [10]
    float* out = (float*)d_out;                    // [4096, 10]

    // Stream-ordered: skew (also resets flags) -> rnn -> fc. Graph-capturable.
    skew_kernel<<<dim3(NCSK / 32, H / 32), dim3(32, 8)>>>(x, w_in, b_in, b_state);
    // 32 blocks <= 148 SMs: whole pipeline co-resident in wave 1, spins safe.
    rnn_kernel<<<NBLK, 64>>>(w_state);
    fc_kernel<<<NROWS / 8, 256>>>(fc_w, fc_b, out);
}

// round 12
// speedup vs baseline: 2.2763x; 1.1425x over previous
#include <cuda_runtime.h>
#include <cstdint>

// Problem constants
#define H      2048
#define W      2048
#define FC_IN  1024
#define FC_OUT 10
#define NROWS  4096          // flat rows = H*W/FC_IN

// RNN pipeline config
#define NBLK   32            // pipeline stages (blocks), 64 rows each
#define CH     16            // columns per chunk
#define NCH    256           // chunks; NCH*CH = 4096 (cols 0..4094 used, 4095 pad)
#define NCSK   4096          // padded skewed width

// Static device scratch (no allocation allowed)
__device__ float g_inp[(size_t)NCSK * H];     // inp_cm[c][r]: scaled affine input, 32 MB
__device__ float g_acts[(size_t)NCSK * H];    // acts_cm[c][r]: h state per skewed col, 32 MB
__device__ float g_bnd[NBLK][NCSK + 64];      // boundary-row stream per block
__device__ int   g_flag[NBLK];                // chunk progress (count of published chunks)

// Acquire probe pairs with writer's st.release.gpu (proven R4/R7/R8).
static __device__ __forceinline__ int ld_acq_i(const int* p) {
    int v; asm volatile("ld.acquire.gpu.global.s32 %0, [%1];" : "=r"(v) : "l"(p)); return v;
}
static __device__ __forceinline__ float ld_cg_f(const float* p) {
    float v; asm volatile("ld.global.cg.f32 %0, [%1];" : "=f"(v) : "l"(p)); return v;
}
static __device__ __forceinline__ void st_rel_i(int* p, int v) {
    asm volatile("st.release.gpu.global.s32 [%0], %1;" :: "l"(p), "r"(v) : "memory");
}

// tanh(y) with z = y * 2*log2(e): tanh(y) = 1 - 2/(1 + 2^z). ~1e-6 accurate.
__device__ __forceinline__ float tanh_core(float z) {
    float e; asm("ex2.approx.f32 %0, %1;" : "=f"(e) : "f"(z));
    float d = e + 1.0f;
    float r; asm("rcp.approx.f32 %0, %1;" : "=f"(r) : "f"(d));
    return fmaf(-2.0f, r, 1.0f);
}

// ---------------------------------------------------------------------------
// Kernel 1: skew + input affine, row-major x -> skewed-column-major g_inp.
// inp_cm[c][r] = wL * (0 <= c-r < W ? x[r][c-r] : 0) + cL.
// Also resets pipeline flags (stream-ordered before rnn_kernel each replay).
// ---------------------------------------------------------------------------
__global__ void __launch_bounds__(256) skew_kernel(
    const float* __restrict__ x,
    const float* __restrict__ w_in, const float* __restrict__ b_in,
    const float* __restrict__ b_state)
{
    __shared__ float xs[32][66];   // pitch 66 -> diagonal smem reads conflict-free

    if (blockIdx.x == 0 && blockIdx.y == 0) {
        int t = threadIdx.y * 32 + threadIdx.x;
        if (t < NBLK) g_flag[t] = 0;
    }

    const float L2E2 = 2.8853900817779268f;   // 2*log2(e)
    const float wL = w_in[0] * L2E2;
    const float cL = (b_state[0] + b_in[0]) * L2E2;

    const int c0 = blockIdx.x * 32;           // skewed-column tile base
    const int r0 = blockIdx.y * 32;           // row tile base
    const int xb = c0 - r0 - 31;              // x-column window base

    for (int rr = threadIdx.y; rr < 32; rr += 8) {
        const float* xrow = x + (size_t)(r0 + rr) * W;
        #pragma unroll
        for (int tt = 0; tt < 2; tt++) {
            int t = threadIdx.x + tt * 32;
            int xc = xb + t;
            xs[rr][t] = ((unsigned)xc < W) ? xrow[xc] : 0.0f;
        }
    }
    __syncthreads();

    for (int cc = threadIdx.y; cc < 32; cc += 8) {
        int rr = threadIdx.x;
        float v = xs[rr][cc - rr + 31];       // = x[r][(c0+cc)-(r0+rr)] or 0
        g_inp[(size_t)(c0 + cc) * H + (r0 + rr)] = fmaf(wL, v, cL);
    }
}

// ---------------------------------------------------------------------------
// Kernel 2: diagonal-wavefront RNN, FULLY WARP-SPECIALIZED. 32 blocks x 3 warps.
// Block b owns rows [64b, 64b+64); compute lane owns rows 2l and 2l+1.
//
// w1 producer: LDG inputs -> smem; acquire-poll pred flag; boundary -> smem
//              (staged BY COLUMN so compute needs no broadcast shfl).
// w0 compute:  pure chain. LDS refills, one SHFL.UP, SEL, 4 FMA, 2 tanh,
//              STS.64 of results. ZERO global memory ops.
// w2 consumer: one chunk behind. Drains staged acts smem -> g_acts (STG.64);
//              lane 31 publishes boundary row + release-stores the flag
//              (own stores precede own release: ordering proven in R4/R7/R8).
// One __syncthreads per chunk rotates all double buffers.
// Steady-state inter-block lag = 2 chunks (w2 publishes chunk k at iter k+1).
// ---------------------------------------------------------------------------
__global__ void __launch_bounds__(96, 1) rnn_kernel(const float* __restrict__ w_state)
{
    __shared__ float2 sin2[2][CH][32];   // staged inputs  [buf][col][lane], 8 KB
    __shared__ float2 sact[2][CH][32];   // staged results [buf][col][lane], 8 KB
    __shared__ float  sbnd[2][CH];       // staged boundary [buf][col]

    const int blk  = blockIdx.x;
    const int wid  = threadIdx.x >> 5;
    const int lane = threadIdx.x & 31;
    const int HP   = H / 2;              // float2 rows per column

    if (wid == 1) {
        // ================= INPUT PRODUCER =================
        const float2* __restrict__ inp2 = ((const float2*)g_inp) + (blk * 32 + lane);
        const int*   fptr = (blk > 0) ? &g_flag[blk - 1] : &g_flag[0];
        const float* bptr = (blk > 0) ? g_bnd[blk - 1]   : g_bnd[0];

        // Prologue: stage chunk 0 (inputs + boundary cols -1..CH-2; col -1 -> 0)
        #pragma unroll
        for (int j = 0; j < CH; j++)
            sin2[0][j][lane] = inp2[(size_t)j * HP];
        if (lane < CH) {
            float b0 = 0.0f;
            if (blk > 0) {
                int fp; do { fp = ld_acq_i(fptr); } while (fp < 1);
                if (lane > 0) b0 = ld_cg_f(bptr + (lane - 1));
            }
            sbnd[0][lane] = b0;
        }
        __syncthreads();

        for (int k = 0; k < NCH; k++) {
            if (k + 1 < NCH) {
                const int nb = (k + 1) & 1;
                const int cn = (k + 1) * CH;
                #pragma unroll
                for (int j = 0; j < CH; j++)
                    sin2[nb][j][lane] = inp2[(size_t)(cn + j) * HP];
                if (lane < CH) {
                    float bv = 0.0f;
                    if (blk > 0) {
                        const int tgt = k + 2;   // cols up to (k+2)*CH-2 needed
                        int fp; do { fp = ld_acq_i(fptr); } while (fp < tgt);
                        bv = ld_cg_f(bptr + (cn - 1 + lane));  // col cn+lane needs bptr[cn-1+lane]
                    }
                    sbnd[nb][lane] = bv;
                }
            }
            __syncthreads();
        }
    } else if (wid == 0) {
        // ================= COMPUTE WARP (no global ops) =================
        const float L2E2 = 2.8853900817779268f;
        const float k0L = w_state[0] * L2E2;   // only 2 tiny const LDGs, prologue
        const float k1L = w_state[1] * L2E2;

        float h0 = 0.0f, h1 = 0.0f;
        __syncthreads();   // buffer 0 ready

        for (int k = 0; k < NCH; k++) {
            const int cb = k & 1;

            float2 pin[CH];
            float  bc[CH];
            #pragma unroll
            for (int j = 0; j < CH; j++) pin[j] = sin2[cb][j][lane];   // LDS.64
            #pragma unroll
            for (int j = 0; j < CH; j++) bc[j]  = sbnd[cb][j];         // broadcast LDS

            #pragma unroll
            for (int j = 0; j < CH; j++) {
                float xn = __shfl_up_sync(0xffffffffu, h1, 1);  // old h[r-1], lanes>0
                if (lane == 0) xn = bc[j];                      // SEL, boundary reg
                float z0 = fmaf(k0L, xn, fmaf(k1L, h0, pin[j].x));
                float z1 = fmaf(k0L, h0, fmaf(k1L, h1, pin[j].y)); // uses OLD h0
                h0 = tanh_core(z0);
                h1 = tanh_core(z1);
                sact[cb][j][lane] = make_float2(h0, h1);        // STS.64, fire-and-forget
            }
            __syncthreads();
        }
    } else {
        // ================= OUTPUT CONSUMER (one chunk behind) =================
        float2* __restrict__ acts2 = ((float2*)g_acts) + (blk * 32 + lane);
        const bool haspub = (blk < NBLK - 1);
        const bool l31    = (lane == 31);

        __syncthreads();   // prologue barrier

        for (int k = 0; k < NCH; k++) {
            if (k > 0) {
                const int pb  = (k - 1) & 1;
                const int c0p = (k - 1) * CH;
                float2 v[CH];
                #pragma unroll
                for (int j = 0; j < CH; j++) v[j] = sact[pb][j][lane];
                float2* ao = acts2 + (size_t)c0p * HP;
                #pragma unroll
                for (int j = 0; j < CH; j++) ao[(size_t)j * HP] = v[j];  // STG.64
                if (l31 && haspub) {
                    #pragma unroll
                    for (int j = 0; j < CH; j++) g_bnd[blk][c0p + j] = v[j].y;
                    st_rel_i(&g_flag[blk], k);   // chunks 0..k-1 published
                }
            }
            __syncthreads();
        }
        // Tail: drain + publish the final chunk (compute/producer have exited;
        // sact was written before the last barrier, so this is race-free).
        {
            const int pb  = (NCH - 1) & 1;
            const int c0p = (NCH - 1) * CH;
            float2 v[CH];
            #pragma unroll
            for (int j = 0; j < CH; j++) v[j] = sact[pb][j][lane];
            float2* ao = acts2 + (size_t)c0p * HP;
            #pragma unroll
            for (int j = 0; j < CH; j++) ao[(size_t)j * HP] = v[j];
            if (l31 && haspub) {
                #pragma unroll
                for (int j = 0; j < CH; j++) g_bnd[blk][c0p + j] = v[j].y;
                st_rel_i(&g_flag[blk], NCH);
            }
        }
    }
}

// ---------------------------------------------------------------------------
// Kernel 3: FC. flat[i][k] = unskewed[r][c] = acts_cm[r + c][r],
// with r = i>>1, c = (i&1)*1024 + k. Warp per output row, weights in smem.
// ---------------------------------------------------------------------------
__global__ void __launch_bounds__(256) fc_kernel(
    const float* __restrict__ fcw, const float* __restrict__ fcb,
    float* __restrict__ out)
{
    __shared__ float ws[FC_OUT * FC_IN];   // 40 KB
    int tid = threadIdx.x;
    for (int i = tid; i < FC_OUT * FC_IN; i += 256) ws[i] = fcw[i];
    __syncthreads();

    int warp = tid >> 5, lane = tid & 31;
    int i = blockIdx.x * 8 + warp;         // flat row 0..4095
    int r = i >> 1, half = i & 1;
    const float* base = g_acts + (size_t)(r + half * FC_IN) * H + r;

    float xv[32];
    #pragma unroll
    for (int m = 0; m < 32; m++) xv[m] = base[(size_t)(lane + 32 * m) * H];

    #pragma unroll
    for (int j = 0; j < FC_OUT; j++) {
        float s = 0.0f;
        #pragma unroll
        for (int m = 0; m < 32; m++)
            s = fmaf(xv[m], ws[j * FC_IN + lane + 32 * m], s);
        #pragma unroll
        for (int o = 16; o > 0; o >>= 1)
            s += __shfl_xor_sync(0xffffffffu, s, o);
        if (lane == 0) out[i * FC_OUT + j] = s + fcb[j];
    }
}

extern "C" void kernel_launch(void* const* d_in, const int* in_sizes, int n_in,
                              void* d_out, int out_size)
{
    const float* x       = (const float*)d_in[0];  // [1, 2048, 2048]
    const float* w_in    = (const float*)d_in[1];  // [1,1,1,1]
    const float* b_in    = (const float*)d_in[2];  // [1]
    const float* w_state = (const float*)d_in[3];  // [1,1,2]
    const float* b_state = (const float*)d_in[4];  // [1]
    const float* fc_w    = (const float*)d_in[5];  // [10, 1024]
    const float* fc_b    = (const float*)d_in[6];  // [10]
    float* out = (float*)d_out;                    // [4096, 10]

    // Stream-ordered: skew (also resets flags) -> rnn -> fc. Graph-capturable.
    skew_kernel<<<dim3(NCSK / 32, H / 32), dim3(32, 8)>>>(x, w_in, b_in, b_state);
    // 32 blocks <= 148 SMs: whole pipeline co-resident in wave 1, spins safe.
    rnn_kernel<<<NBLK, 96>>>(w_state);
    fc_kernel<<<NROWS / 8, 256>>>(fc_w, fc_b, out);
}

// round 13
// speedup vs baseline: 2.6074x; 1.1454x over previous
#include <cuda_runtime.h>
#include <cstdint>

// Problem constants
#define H      2048
#define W      2048
#define FC_IN  1024
#define FC_OUT 10
#define NROWS  4096          // flat rows = H*W/FC_IN

// RNN pipeline config
#define NBLK   32            // pipeline stages (blocks), 64 rows each
#define CH     16            // columns per chunk
#define NCH    256           // chunks; NCH*CH = 4096 (cols 0..4094 used, 4095 pad)
#define NCSK   4096          // padded skewed width

// Static device scratch (no allocation allowed)
__device__ float g_inp[(size_t)NCSK * H];     // inp_cm[c][r] = w*x+b, 32 MB
__device__ float g_acts[(size_t)NCSK * H];    // acts_cm[c][r]: h state per skewed col, 32 MB
__device__ float g_bnd[NBLK][NCSK + 64];      // boundary-row stream per block
__device__ int   g_flag[NBLK];                // chunk progress (count of published chunks)

// Acquire probe pairs with writer's st.release.gpu (proven R4/R7/R8/R9).
static __device__ __forceinline__ int ld_acq_i(const int* p) {
    int v; asm volatile("ld.acquire.gpu.global.s32 %0, [%1];" : "=r"(v) : "l"(p)); return v;
}
static __device__ __forceinline__ float ld_cg_f(const float* p) {
    float v; asm volatile("ld.global.cg.f32 %0, [%1];" : "=f"(v) : "l"(p)); return v;
}
static __device__ __forceinline__ void st_rel_i(int* p, int v) {
    asm volatile("st.release.gpu.global.s32 [%0], %1;" :: "l"(p), "r"(v) : "memory");
}

// Hardware tanh: single MUFU.TANH, lat ~16 (vs 40-cy ex2/add/rcp/fma chain).
// Per-step rel error ~4.9e-4; measured pipeline attenuation is 0.32x
// (1e-6-accurate tanh gave final rel_err 3.2e-7), so predicted final
// rel_err ~1.6e-4 -- 6x inside the 1e-3 gate.
static __device__ __forceinline__ float tanh_hw(float y) {
    float r; asm("tanh.approx.f32 %0, %1;" : "=f"(r) : "f"(y));
    return r;
}

// ---------------------------------------------------------------------------
// Kernel 1: skew + input affine, row-major x -> skewed-column-major g_inp.
// inp_cm[c][r] = w * (0 <= c-r < W ? x[r][c-r] : 0) + b   (NO pre-scaling now).
// Also resets pipeline flags (stream-ordered before rnn_kernel each replay).
// ---------------------------------------------------------------------------
__global__ void __launch_bounds__(256) skew_kernel(
    const float* __restrict__ x,
    const float* __restrict__ w_in, const float* __restrict__ b_in,
    const float* __restrict__ b_state)
{
    __shared__ float xs[32][66];   // pitch 66 -> diagonal smem reads conflict-free

    if (blockIdx.x == 0 && blockIdx.y == 0) {
        int t = threadIdx.y * 32 + threadIdx.x;
        if (t < NBLK) g_flag[t] = 0;
    }

    const float wL = w_in[0];
    const float cL = b_state[0] + b_in[0];

    const int c0 = blockIdx.x * 32;           // skewed-column tile base
    const int r0 = blockIdx.y * 32;           // row tile base
    const int xb = c0 - r0 - 31;              // x-column window base

    for (int rr = threadIdx.y; rr < 32; rr += 8) {
        const float* xrow = x + (size_t)(r0 + rr) * W;
        #pragma unroll
        for (int tt = 0; tt < 2; tt++) {
            int t = threadIdx.x + tt * 32;
            int xc = xb + t;
            xs[rr][t] = ((unsigned)xc < W) ? xrow[xc] : 0.0f;
        }
    }
    __syncthreads();

    for (int cc = threadIdx.y; cc < 32; cc += 8) {
        int rr = threadIdx.x;
        float v = xs[rr][cc - rr + 31];       // = x[r][(c0+cc)-(r0+rr)] or 0
        g_inp[(size_t)(c0 + cc) * H + (r0 + rr)] = fmaf(wL, v, cL);
    }
}

// ---------------------------------------------------------------------------
// Kernel 2: diagonal-wavefront RNN, FULLY WARP-SPECIALIZED. 32 blocks x 3 warps.
// Block b owns rows [64b, 64b+64); compute lane owns rows 2l and 2l+1.
//
// w1 producer: LDG inputs -> smem; acquire-poll pred flag; boundary -> smem
//              (staged BY COLUMN so compute needs no broadcast shfl).
// w0 compute:  pure chain. LDS refills, one SHFL.UP, SEL, 4 FMA, 2 MUFU.TANH,
//              STS.64 of results. ZERO global memory ops.
// w2 consumer: one chunk behind. Drains staged acts smem -> g_acts (STG.64);
//              lane 31 publishes boundary row + release-stores the flag.
// One __syncthreads per chunk rotates all double buffers.
// ---------------------------------------------------------------------------
__global__ void __launch_bounds__(96, 1) rnn_kernel(const float* __restrict__ w_state)
{
    __shared__ float2 sin2[2][CH][32];   // staged inputs  [buf][col][lane], 8 KB
    __shared__ float2 sact[2][CH][32];   // staged results [buf][col][lane], 8 KB
    __shared__ float  sbnd[2][CH];       // staged boundary [buf][col]

    const int blk  = blockIdx.x;
    const int wid  = threadIdx.x >> 5;
    const int lane = threadIdx.x & 31;
    const int HP   = H / 2;              // float2 rows per column

    if (wid == 1) {
        // ================= INPUT PRODUCER =================
        const float2* __restrict__ inp2 = ((const float2*)g_inp) + (blk * 32 + lane);
        const int*   fptr = (blk > 0) ? &g_flag[blk - 1] : &g_flag[0];
        const float* bptr = (blk > 0) ? g_bnd[blk - 1]   : g_bnd[0];

        // Prologue: stage chunk 0 (inputs + boundary cols -1..CH-2; col -1 -> 0)
        #pragma unroll
        for (int j = 0; j < CH; j++)
            sin2[0][j][lane] = inp2[(size_t)j * HP];
        if (lane < CH) {
            float b0 = 0.0f;
            if (blk > 0) {
                int fp; do { fp = ld_acq_i(fptr); } while (fp < 1);
                if (lane > 0) b0 = ld_cg_f(bptr + (lane - 1));
            }
            sbnd[0][lane] = b0;
        }
        __syncthreads();

        for (int k = 0; k < NCH; k++) {
            if (k + 1 < NCH) {
                const int nb = (k + 1) & 1;
                const int cn = (k + 1) * CH;
                #pragma unroll
                for (int j = 0; j < CH; j++)
                    sin2[nb][j][lane] = inp2[(size_t)(cn + j) * HP];
                if (lane < CH) {
                    float bv = 0.0f;
                    if (blk > 0) {
                        const int tgt = k + 2;   // cols up to (k+2)*CH-2 needed
                        int fp; do { fp = ld_acq_i(fptr); } while (fp < tgt);
                        bv = ld_cg_f(bptr + (cn - 1 + lane));
                    }
                    sbnd[nb][lane] = bv;
                }
            }
            __syncthreads();
        }
    } else if (wid == 0) {
        // ================= COMPUTE WARP (no global ops) =================
        const float k0 = w_state[0];   // only 2 tiny const LDGs, prologue
        const float k1 = w_state[1];

        float h0 = 0.0f, h1 = 0.0f;
        __syncthreads();   // buffer 0 ready

        for (int k = 0; k < NCH; k++) {
            const int cb = k & 1;

            float2 pin[CH];
            float  bc[CH];
            #pragma unroll
            for (int j = 0; j < CH; j++) pin[j] = sin2[cb][j][lane];   // LDS.64
            #pragma unroll
            for (int j = 0; j < CH; j++) bc[j]  = sbnd[cb][j];         // broadcast LDS

            #pragma unroll
            for (int j = 0; j < CH; j++) {
                float xn = __shfl_up_sync(0xffffffffu, h1, 1);  // old h[r-1], lanes>0
                if (lane == 0) xn = bc[j];                      // SEL, boundary reg
                float t0 = fmaf(k1, h0, pin[j].x);              // off shfl path
                float t1 = fmaf(k1, h1, pin[j].y);
                float z0 = fmaf(k0, xn, t0);
                float z1 = fmaf(k0, h0, t1);                    // uses OLD h0
                h0 = tanh_hw(z0);                               // MUFU.TANH
                h1 = tanh_hw(z1);
                sact[cb][j][lane] = make_float2(h0, h1);        // STS.64
            }
            __syncthreads();
        }
    } else {
        // ================= OUTPUT CONSUMER (one chunk behind) =================
        float2* __restrict__ acts2 = ((float2*)g_acts) + (blk * 32 + lane);
        const bool haspub = (blk < NBLK - 1);
        const bool l31    = (lane == 31);

        __syncthreads();   // prologue barrier

        for (int k = 0; k < NCH; k++) {
            if (k > 0) {
                const int pb  = (k - 1) & 1;
                const int c0p = (k - 1) * CH;
                float2 v[CH];
                #pragma unroll
                for (int j = 0; j < CH; j++) v[j] = sact[pb][j][lane];
                float2* ao = acts2 + (size_t)c0p * HP;
                #pragma unroll
                for (int j = 0; j < CH; j++) ao[(size_t)j * HP] = v[j];  // STG.64
                if (l31 && haspub) {
                    #pragma unroll
                    for (int j = 0; j < CH; j++) g_bnd[blk][c0p + j] = v[j].y;
                    st_rel_i(&g_flag[blk], k);   // chunks 0..k-1 published
                }
            }
            __syncthreads();
        }
        // Tail: drain + publish the final chunk (sact written before last barrier).
        {
            const int pb  = (NCH - 1) & 1;
            const int c0p = (NCH - 1) * CH;
            float2 v[CH];
            #pragma unroll
            for (int j = 0; j < CH; j++) v[j] = sact[pb][j][lane];
            float2* ao = acts2 + (size_t)c0p * HP;
            #pragma unroll
            for (int j = 0; j < CH; j++) ao[(size_t)j * HP] = v[j];
            if (l31 && haspub) {
                #pragma unroll
                for (int j = 0; j < CH; j++) g_bnd[blk][c0p + j] = v[j].y;
                st_rel_i(&g_flag[blk], NCH);
            }
        }
    }
}

// ---------------------------------------------------------------------------
// Kernel 3: FC. flat[i][k] = unskewed[r][c] = acts_cm[r + c][r],
// with r = i>>1, c = (i&1)*1024 + k. Warp per output row, weights in smem.
// ---------------------------------------------------------------------------
__global__ void __launch_bounds__(256) fc_kernel(
    const float* __restrict__ fcw, const float* __restrict__ fcb,
    float* __restrict__ out)
{
    __shared__ float ws[FC_OUT * FC_IN];   // 40 KB
    int tid = threadIdx.x;
    for (int i = tid; i < FC_OUT * FC_IN; i += 256) ws[i] = fcw[i];
    __syncthreads();

    int warp = tid >> 5, lane = tid & 31;
    int i = blockIdx.x * 8 + warp;         // flat row 0..4095
    int r = i >> 1, half = i & 1;
    const float* base = g_acts + (size_t)(r + half * FC_IN) * H + r;

    float xv[32];
    #pragma unroll
    for (int m = 0; m < 32; m++) xv[m] = base[(size_t)(lane + 32 * m) * H];

    #pragma unroll
    for (int j = 0; j < FC_OUT; j++) {
        float s = 0.0f;
        #pragma unroll
        for (int m = 0; m < 32; m++)
            s = fmaf(xv[m], ws[j * FC_IN + lane + 32 * m], s);
        #pragma unroll
        for (int o = 16; o > 0; o >>= 1)
            s += __shfl_xor_sync(0xffffffffu, s, o);
        if (lane == 0) out[i * FC_OUT + j] = s + fcb[j];
    }
}

extern "C" void kernel_launch(void* const* d_in, const int* in_sizes, int n_in,
                              void* d_out, int out_size)
{
    const float* x       = (const float*)d_in[0];  // [1, 2048, 2048]
    const float* w_in    = (const float*)d_in[1];  // [1,1,1,1]
    const float* b_in    = (const float*)d_in[2];  // [1]
    const float* w_state = (const float*)d_in[3];  // [1,1,2]
    const float* b_state = (const float*)d_in[4];  // [1]
    const float* fc_w    = (const float*)d_in[5];  // [10, 1024]
    const float* fc_b    = (const float*)d_in[6];  // [10]
    float* out = (float*)d_out;                    // [4096, 10]

    // Stream-ordered: skew (also resets flags) -> rnn -> fc. Graph-capturable.
    skew_kernel<<<dim3(NCSK / 32, H / 32), dim3(32, 8)>>>(x, w_in, b_in, b_state);
    // 32 blocks <= 148 SMs: whole pipeline co-resident in wave 1, spins safe.
    rnn_kernel<<<NBLK, 96>>>(w_state);
    fc_kernel<<<NROWS / 8, 256>>>(fc_w, fc_b, out);
}

// round 14
// speedup vs baseline: 2.6847x; 1.0296x over previous
#include <cuda_runtime.h>
#include <cstdint>

// Problem constants
#define H      2048
#define W      2048
#define FC_IN  1024
#define FC_OUT 10
#define NROWS  4096          // flat rows = H*W/FC_IN

// RNN pipeline config
#define NBLK   32            // pipeline stages (blocks), 64 rows each
#define CH     16            // columns per chunk
#define NCH    256           // chunks; NCH*CH = 4096 (cols 0..4094 used, 4095 pad)
#define NCSK   4096          // padded skewed width

// Static device scratch (no allocation allowed)
__device__ float g_inp[(size_t)NCSK * H];     // inp_cm[c][r] = w*x+b, 32 MB
__device__ float g_uns[(size_t)H * W];        // UNSKEWED activations, row-major, 16 MB
__device__ float g_bnd[NBLK][NCSK + 64];      // boundary-row stream per block
__device__ int   g_flag[NBLK];                // chunk progress (count of published chunks)

// Acquire probe pairs with writer's st.release.gpu (proven R4/R7/R8/R9/R12).
static __device__ __forceinline__ int ld_acq_i(const int* p) {
    int v; asm volatile("ld.acquire.gpu.global.s32 %0, [%1];" : "=r"(v) : "l"(p)); return v;
}
static __device__ __forceinline__ float ld_cg_f(const float* p) {
    float v; asm volatile("ld.global.cg.f32 %0, [%1];" : "=f"(v) : "l"(p)); return v;
}
static __device__ __forceinline__ void st_rel_i(int* p, int v) {
    asm volatile("st.release.gpu.global.s32 [%0], %1;" :: "l"(p), "r"(v) : "memory");
}

// Hardware tanh: single MUFU.TANH. Measured final rel_err 2.86e-6 (R12).
static __device__ __forceinline__ float tanh_hw(float y) {
    float r; asm("tanh.approx.f32 %0, %1;" : "=f"(r) : "f"(y));
    return r;
}

// ---------------------------------------------------------------------------
// Kernel 1: skew + input affine, row-major x -> skewed-column-major g_inp.
// inp_cm[c][r] = w * (0 <= c-r < W ? x[r][c-r] : 0) + b.
// Also resets pipeline flags (stream-ordered before rnn_kernel each replay).
// ---------------------------------------------------------------------------
__global__ void __launch_bounds__(256) skew_kernel(
    const float* __restrict__ x,
    const float* __restrict__ w_in, const float* __restrict__ b_in,
    const float* __restrict__ b_state)
{
    __shared__ float xs[32][66];   // pitch 66 -> diagonal smem reads conflict-free

    if (blockIdx.x == 0 && blockIdx.y == 0) {
        int t = threadIdx.y * 32 + threadIdx.x;
        if (t < NBLK) g_flag[t] = 0;
    }

    const float wL = w_in[0];
    const float cL = b_state[0] + b_in[0];

    const int c0 = blockIdx.x * 32;           // skewed-column tile base
    const int r0 = blockIdx.y * 32;           // row tile base
    const int xb = c0 - r0 - 31;              // x-column window base

    for (int rr = threadIdx.y; rr < 32; rr += 8) {
        const float* xrow = x + (size_t)(r0 + rr) * W;
        #pragma unroll
        for (int tt = 0; tt < 2; tt++) {
            int t = threadIdx.x + tt * 32;
            int xc = xb + t;
            xs[rr][t] = ((unsigned)xc < W) ? xrow[xc] : 0.0f;
        }
    }
    __syncthreads();

    for (int cc = threadIdx.y; cc < 32; cc += 8) {
        int rr = threadIdx.x;
        float v = xs[rr][cc - rr + 31];       // = x[r][(c0+cc)-(r0+rr)] or 0
        g_inp[(size_t)(c0 + cc) * H + (r0 + rr)] = fmaf(wL, v, cL);
    }
}

// ---------------------------------------------------------------------------
// Kernel 2: diagonal-wavefront RNN, FULLY WARP-SPECIALIZED. 32 blocks x 3 warps.
// Block b owns rows [64b, 64b+64); compute lane owns rows 2l and 2l+1.
//
// w1 producer: LDG inputs -> smem; acquire-poll pred flag; boundary -> smem.
// w0 compute:  pure chain — LDS refills, one SHFL.UP, SEL, 4 FMA, 2 MUFU.TANH,
//              STS.64 of results. ZERO global memory ops.
// w2 consumer: one chunk behind. NEW: writes results directly to the UNSKEWED
//              row-major image (unskewed[r][c-r]; for fixed r a chunk is 16
//              contiguous floats) — kills fc's strided gather entirely.
//              Lane 31 publishes boundary row + release-stores the flag.
// ---------------------------------------------------------------------------
__global__ void __launch_bounds__(96, 1) rnn_kernel(const float* __restrict__ w_state)
{
    __shared__ float2 sin2[2][CH][32];   // staged inputs  [buf][col][lane], 8 KB
    __shared__ float2 sact[2][CH][32];   // staged results [buf][col][lane], 8 KB
    __shared__ float  sbnd[2][CH];       // staged boundary [buf][col]

    const int blk  = blockIdx.x;
    const int wid  = threadIdx.x >> 5;
    const int lane = threadIdx.x & 31;
    const int HP   = H / 2;              // float2 rows per column

    if (wid == 1) {
        // ================= INPUT PRODUCER =================
        const float2* __restrict__ inp2 = ((const float2*)g_inp) + (blk * 32 + lane);
        const int*   fptr = (blk > 0) ? &g_flag[blk - 1] : &g_flag[0];
        const float* bptr = (blk > 0) ? g_bnd[blk - 1]   : g_bnd[0];

        // Prologue: stage chunk 0 (inputs + boundary cols -1..CH-2; col -1 -> 0)
        #pragma unroll
        for (int j = 0; j < CH; j++)
            sin2[0][j][lane] = inp2[(size_t)j * HP];
        if (lane < CH) {
            float b0 = 0.0f;
            if (blk > 0) {
                int fp; do { fp = ld_acq_i(fptr); } while (fp < 1);
                if (lane > 0) b0 = ld_cg_f(bptr + (lane - 1));
            }
            sbnd[0][lane] = b0;
        }
        __syncthreads();

        for (int k = 0; k < NCH; k++) {
            if (k + 1 < NCH) {
                const int nb = (k + 1) & 1;
                const int cn = (k + 1) * CH;
                #pragma unroll
                for (int j = 0; j < CH; j++)
                    sin2[nb][j][lane] = inp2[(size_t)(cn + j) * HP];
                if (lane < CH) {
                    float bv = 0.0f;
                    if (blk > 0) {
                        const int tgt = k + 2;   // cols up to (k+2)*CH-2 needed
                        int fp; do { fp = ld_acq_i(fptr); } while (fp < tgt);
                        bv = ld_cg_f(bptr + (cn - 1 + lane));
                    }
                    sbnd[nb][lane] = bv;
                }
            }
            __syncthreads();
        }
    } else if (wid == 0) {
        // ================= COMPUTE WARP (no global ops) =================
        const float k0 = w_state[0];   // only 2 tiny const LDGs, prologue
        const float k1 = w_state[1];

        float h0 = 0.0f, h1 = 0.0f;
        __syncthreads();   // buffer 0 ready

        for (int k = 0; k < NCH; k++) {
            const int cb = k & 1;

            float2 pin[CH];
            float  bc[CH];
            #pragma unroll
            for (int j = 0; j < CH; j++) pin[j] = sin2[cb][j][lane];   // LDS.64
            #pragma unroll
            for (int j = 0; j < CH; j++) bc[j]  = sbnd[cb][j];         // broadcast LDS

            #pragma unroll
            for (int j = 0; j < CH; j++) {
                float xn = __shfl_up_sync(0xffffffffu, h1, 1);  // old h[r-1], lanes>0
                if (lane == 0) xn = bc[j];                      // SEL, boundary reg
                float t0 = fmaf(k1, h0, pin[j].x);              // off shfl path
                float t1 = fmaf(k1, h1, pin[j].y);
                float z0 = fmaf(k0, xn, t0);
                float z1 = fmaf(k0, h0, t1);                    // uses OLD h0
                h0 = tanh_hw(z0);                               // MUFU.TANH
                h1 = tanh_hw(z1);
                sact[cb][j][lane] = make_float2(h0, h1);        // STS.64
            }
            __syncthreads();
        }
    } else {
        // ================= OUTPUT CONSUMER (one chunk behind) =================
        // Lane owns rows R0 = 64*blk + 2*lane (even) and R1 = R0+1 (odd).
        // unskewed[r][c - r]: for a chunk, 16 consecutive elements per row.
        const int R0 = blk * 64 + 2 * lane;
        const int R1 = R0 + 1;
        float* __restrict__ row0 = g_uns + (size_t)R0 * W;
        float* __restrict__ row1 = g_uns + (size_t)R1 * W;
        const bool haspub = (blk < NBLK - 1);
        const bool l31    = (lane == 31);

        __syncthreads();   // prologue barrier

        for (int k = 0; k <= NCH; k++) {
            if (k > 0) {
                const int pb  = (k - 1) & 1;
                const int c0p = (k - 1) * CH;
                float2 v[CH];
                #pragma unroll
                for (int j = 0; j < CH; j++) v[j] = sact[pb][j][lane];

                // Even row: base e0 = c0p - R0 is even -> aligned float2 pairs,
                // pair valid iff e in [0, W) (e even, so e <= W-2 when valid).
                const int e0 = c0p - R0;
                #pragma unroll
                for (int t = 0; t < CH / 2; t++) {
                    int e = e0 + 2 * t;
                    if ((unsigned)e < W)
                        *(float2*)(row0 + e) = make_float2(v[2 * t].x, v[2 * t + 1].x);
                }
                // Odd row: odd base -> scalar stores.
                const int e1 = c0p - R1;
                #pragma unroll
                for (int j = 0; j < CH; j++) {
                    int e = e1 + j;
                    if ((unsigned)e < W) row1[e] = v[j].y;
                }

                if (l31 && haspub) {
                    #pragma unroll
                    for (int j = 0; j < CH; j++) g_bnd[blk][c0p + j] = v[j].y;
                    st_rel_i(&g_flag[blk], k);   // chunks 0..k-1 published
                }
            }
            if (k < NCH) __syncthreads();
            // k == NCH is the tail drain: sact was written before the final
            // barrier of the compute warp, so reading it here is race-free.
        }
    }
}

// ---------------------------------------------------------------------------
// Kernel 3: FC, now fully coalesced. g_uns row-major flattened IS
// flat[4096][1024]. Warp per output row, weights in smem.
// ---------------------------------------------------------------------------
__global__ void __launch_bounds__(256) fc_kernel(
    const float* __restrict__ fcw, const float* __restrict__ fcb,
    float* __restrict__ out)
{
    __shared__ float ws[FC_OUT * FC_IN];   // 40 KB
    int tid = threadIdx.x;
    for (int i = tid; i < FC_OUT * FC_IN; i += 256) ws[i] = fcw[i];
    __syncthreads();

    int warp = tid >> 5, lane = tid & 31;
    int i = blockIdx.x * 8 + warp;         // flat row 0..4095
    const float* xr = g_uns + (size_t)i * FC_IN;

    float xv[32];
    #pragma unroll
    for (int m = 0; m < 32; m++) xv[m] = xr[lane + 32 * m];   // coalesced

    #pragma unroll
    for (int j = 0; j < FC_OUT; j++) {
        float s = 0.0f;
        #pragma unroll
        for (int m = 0; m < 32; m++)
            s = fmaf(xv[m], ws[j * FC_IN + lane + 32 * m], s);
        #pragma unroll
        for (int o = 16; o > 0; o >>= 1)
            s += __shfl_xor_sync(0xffffffffu, s, o);
        if (lane == 0) out[i * FC_OUT + j] = s + fcb[j];
    }
}

extern "C" void kernel_launch(void* const* d_in, const int* in_sizes, int n_in,
                              void* d_out, int out_size)
{
    const float* x       = (const float*)d_in[0];  // [1, 2048, 2048]
    const float* w_in    = (const float*)d_in[1];  // [1,1,1,1]
    const float* b_in    = (const float*)d_in[2];  // [1]
    const float* w_state = (const float*)d_in[3];  // [1,1,2]
    const float* b_state = (const float*)d_in[4];  // [1]
    const float* fc_w    = (const float*)d_in[5];  // [10, 1024]
    const float* fc_b    = (const float*)d_in[6];  // [10]
    float* out = (float*)d_out;                    // [4096, 10]

    // Stream-ordered: skew (also resets flags) -> rnn -> fc. Graph-capturable.
    skew_kernel<<<dim3(NCSK / 32, H / 32), dim3(32, 8)>>>(x, w_in, b_in, b_state);
    // 32 blocks <= 148 SMs: whole pipeline co-resident in wave 1, spins safe.
    rnn_kernel<<<NBLK, 96>>>(w_state);
    fc_kernel<<<NROWS / 8, 256>>>(fc_w, fc_b, out);
}